// round 15
// baseline (speedup 1.0000x reference)
#include <cuda_runtime.h>
#include <cuda_fp16.h>
#include <cstdint>

// Problem constants
#define BB 4
#define TT 2048
#define HH 2048
#define DD 4
#define FFN 8192
#define MM (BB * TT)          // 8192 tokens

// Scratch (device globals: allocation-free per harness rules)
__device__ __half g_hh  [MM * HH];        // h (LN1) -> later h2 (LN2)
__device__ __half g_att [MM * HH];        // attin -> later km
__device__ __half g_kkh [MM * FFN];       // kk (half)
__device__ __half g_qkv [MM * 3 * HH];    // fused v|k|r outputs
__device__ float  g_vg  [MM * 2 * HH];    // fused val|gate outputs
__device__ float  g_x1  [MM * HH];        // x1
__device__ float  g_lw  [MM * DD];        // level softmax weights
__device__ float  g_dec [DD * HH];        // decay
// Transposed fp16 weights ([N,K] row-major for mma.sync row.col B operand)
__device__ __half g_WqkvT[3 * HH * HH];   // WvT | WkT | WrT (row blocks)
__device__ __half g_WoT  [HH * HH];
__device__ __half g_WkeyT[FFN * HH];
__device__ __half g_WvgT [2 * HH * FFN];  // WvalT | WgateT (row blocks)

// ---------------------------------------------------------------------------
__device__ __forceinline__ void mma_f16(float c[4], const uint32_t a[4], const uint32_t b[2]) {
    asm volatile(
        "mma.sync.aligned.m16n8k16.row.col.f32.f16.f16.f32 "
        "{%0,%1,%2,%3}, {%4,%5,%6,%7}, {%8,%9}, {%0,%1,%2,%3};"
        : "+f"(c[0]), "+f"(c[1]), "+f"(c[2]), "+f"(c[3])
        : "r"(a[0]), "r"(a[1]), "r"(a[2]), "r"(a[3]), "r"(b[0]), "r"(b[1]));
}

__device__ __forceinline__ void ldsm_x4(uint32_t& r0, uint32_t& r1, uint32_t& r2, uint32_t& r3,
                                        uint32_t addr) {
    asm volatile("ldmatrix.sync.aligned.m8n8.x4.shared.b16 {%0,%1,%2,%3}, [%4];"
                 : "=r"(r0), "=r"(r1), "=r"(r2), "=r"(r3) : "r"(addr));
}

__device__ __forceinline__ void cp_async16(uint32_t smem_addr, const void* gptr) {
    asm volatile("cp.async.ca.shared.global [%0], [%1], 16;" :: "r"(smem_addr), "l"(gptr));
}
__device__ __forceinline__ void cp_commit() {
    asm volatile("cp.async.commit_group;" ::: "memory");
}
__device__ __forceinline__ void cp_wait_all() {
    asm volatile("cp.async.wait_group 0;" ::: "memory");
}

// ===========================================================================
// Tensor-core fp16 GEMM (fp32 accum): C[M,N] = A[M,K] @ Bt[N,K]^T
// Block tile 128x128, BK=64, 128 threads (4 warps = 2x2), warp tile 64x64.
// 2-stage cp.async pipeline + double-buffered ldmatrix fragments.
// Stage layout: 256 rows (128 A + 128 B) x 36 uints (64 halfs + 4 pad).
// EPI: 0 plain, 1 +Res(float), 2 relu(.)^2.  OutT: float or __half.
// Requires M%128==0, N%128==0, K%64==0.
// ===========================================================================
#define STAGE_BYTES 36864          // 256 * 144
#define GEMM_SMEM (2 * STAGE_BYTES)

template <int EPI, typename OutT>
__global__ __launch_bounds__(128, 2) void mma_gemm_kernel(
    const __half* __restrict__ A, const __half* __restrict__ Bt,
    const float* __restrict__ Res, OutT* __restrict__ C,
    int M, int N, int K)
{
    extern __shared__ uint32_t smem[];
    const uint32_t smem_base = (uint32_t)__cvta_generic_to_shared(smem);

    const int tid = threadIdx.x;
    const int wid = tid >> 5, lane = tid & 31;
    const int wm = wid & 1, wn = wid >> 1;        // 2(m) x 2(n) warp grid
    const int group = lane >> 2, tg = lane & 3;   // mma fragment coords
    const int bm = blockIdx.y * 128, bn = blockIdx.x * 128;

    const __half* Arow = A  + (size_t)(bm + tid) * K;
    const __half* Brow = Bt + (size_t)(bn + tid) * K;
    const uint32_t sA = smem_base + tid * 144;
    const uint32_t sB = smem_base + (128 + tid) * 144;

    const int arow_l = wm * 64 + (lane & 7) + ((lane >> 3) & 1) * 8;
    const int acol_l = (lane >> 4) << 2;
    const int brow_l = wn * 64 + ((lane >> 4) << 3) + (lane & 7);
    const int bcol_l = ((lane >> 3) & 1) << 2;
    const uint32_t aoff = (uint32_t)(arow_l * 144 + acol_l * 4);
    const uint32_t boff = (uint32_t)((128 + brow_l) * 144 + bcol_l * 4);

    auto load_async = [&](int k0, int st) {
        const uint32_t off = (uint32_t)st * STAGE_BYTES;
#pragma unroll
        for (int cg = 0; cg < 8; cg++) {
            cp_async16(sA + off + cg * 16, Arow + k0 + cg * 8);
            cp_async16(sB + off + cg * 16, Brow + k0 + cg * 8);
        }
        cp_commit();
    };

    // load fragments for one k16 block (byte offset kb = j*32) of stage st
    auto ldfrag = [&](int st, int kb, uint32_t af[4][4], uint32_t bf[8][2]) {
        const uint32_t sb = smem_base + (uint32_t)st * STAGE_BYTES + (uint32_t)kb;
#pragma unroll
        for (int mi = 0; mi < 4; mi++)
            ldsm_x4(af[mi][0], af[mi][1], af[mi][2], af[mi][3], sb + aoff + mi * 2304);
#pragma unroll
        for (int p = 0; p < 4; p++)
            ldsm_x4(bf[2 * p][0], bf[2 * p][1], bf[2 * p + 1][0], bf[2 * p + 1][1],
                    sb + boff + p * 2304);
    };

    float c[4][8][4];
#pragma unroll
    for (int mi = 0; mi < 4; mi++)
#pragma unroll
        for (int ni = 0; ni < 8; ni++)
#pragma unroll
            for (int j = 0; j < 4; j++) c[mi][ni][j] = 0.f;

    auto compute = [&](uint32_t af[4][4], uint32_t bf[8][2]) {
#pragma unroll
        for (int mi = 0; mi < 4; mi++)
#pragma unroll
            for (int ni = 0; ni < 8; ni++)
                mma_f16(c[mi][ni], af[mi], bf[ni]);
    };

    const int nt = K >> 6;
    load_async(0, 0);
    cp_wait_all();
    __syncthreads();

    uint32_t af[2][4][4], bf[2][8][2];
    ldfrag(0, 0, af[0], bf[0]);

    for (int t = 0; t < nt; ++t) {
        const int st = t & 1;
        if (t + 1 < nt) load_async((t + 1) << 6, st ^ 1);
#pragma unroll
        for (int j = 0; j < 4; ++j) {
            if (j < 3) ldfrag(st, (j + 1) * 32, af[(j + 1) & 1], bf[(j + 1) & 1]);
            compute(af[j & 1], bf[j & 1]);
        }
        if (t + 1 < nt) {
            cp_wait_all();
            __syncthreads();
            ldfrag(st ^ 1, 0, af[0], bf[0]);
        }
    }

    // epilogue
#pragma unroll
    for (int mi = 0; mi < 4; mi++) {
        const int m0 = bm + wm * 64 + mi * 16 + group;
#pragma unroll
        for (int ni = 0; ni < 8; ni++) {
            const int n0 = bn + wn * 64 + ni * 8 + tg * 2;
            float2 lo = make_float2(c[mi][ni][0], c[mi][ni][1]);
            float2 hi = make_float2(c[mi][ni][2], c[mi][ni][3]);
            if (EPI == 1) {
                const float2 r0 = *(const float2*)(Res + (size_t)m0 * N + n0);
                const float2 r1 = *(const float2*)(Res + (size_t)(m0 + 8) * N + n0);
                lo.x += r0.x; lo.y += r0.y; hi.x += r1.x; hi.y += r1.y;
            }
            if (EPI == 2) {
                lo.x = fmaxf(lo.x, 0.f); lo.x *= lo.x;
                lo.y = fmaxf(lo.y, 0.f); lo.y *= lo.y;
                hi.x = fmaxf(hi.x, 0.f); hi.x *= hi.x;
                hi.y = fmaxf(hi.y, 0.f); hi.y *= hi.y;
            }
            if (sizeof(OutT) == 2) {
                *(__half2*)((__half*)C + (size_t)m0 * N + n0)       = __floats2half2_rn(lo.x, lo.y);
                *(__half2*)((__half*)C + (size_t)(m0 + 8) * N + n0) = __floats2half2_rn(hi.x, hi.y);
            } else {
                *(float2*)((float*)C + (size_t)m0 * N + n0)       = lo;
                *(float2*)((float*)C + (size_t)(m0 + 8) * N + n0) = hi;
            }
        }
    }
}

// ---------------------------------------------------------------------------
// Batched transpose + fp16 convert: in[z][R,C] fp32 -> out[z][C,R] fp16
// ---------------------------------------------------------------------------
__global__ __launch_bounds__(256) void transpose_h4_kernel(
    const float* i0, const float* i1, const float* i2, const float* i3,
    __half* o0, __half* o1, __half* o2, __half* o3, int R, int C)
{
    const int z = blockIdx.z;
    const float* in = (z == 0) ? i0 : (z == 1) ? i1 : (z == 2) ? i2 : i3;
    __half* out     = (z == 0) ? o0 : (z == 1) ? o1 : (z == 2) ? o2 : o3;
    __shared__ float tile[32][33];
    const int c0 = blockIdx.x * 32, r0 = blockIdx.y * 32;
    for (int i = threadIdx.y; i < 32; i += 8)
        tile[i][threadIdx.x] = in[(size_t)(r0 + i) * C + c0 + threadIdx.x];
    __syncthreads();
    for (int i = threadIdx.y; i < 32; i += 8)
        out[(size_t)(c0 + i) * R + r0 + threadIdx.x] = __float2half(tile[threadIdx.x][i]);
}

// ---------------------------------------------------------------------------
// Single-pass LayerNorm -> fp16: row cached in registers (8 floats/thread)
// ---------------------------------------------------------------------------
__global__ __launch_bounds__(256) void ln_kernel(
    const float* __restrict__ x, const float* __restrict__ s,
    const float* __restrict__ bvec, __half* __restrict__ out)
{
    const int row = blockIdx.x;
    const int t = threadIdx.x;
    const float4* xr = (const float4*)(x + (size_t)row * HH);
    const float4 v0 = xr[t * 2], v1 = xr[t * 2 + 1];
    float sum = v0.x + v0.y + v0.z + v0.w + v1.x + v1.y + v1.z + v1.w;
    float sq  = v0.x * v0.x + v0.y * v0.y + v0.z * v0.z + v0.w * v0.w
              + v1.x * v1.x + v1.y * v1.y + v1.z * v1.z + v1.w * v1.w;
    for (int o = 16; o; o >>= 1) {
        sum += __shfl_down_sync(0xffffffffu, sum, o);
        sq  += __shfl_down_sync(0xffffffffu, sq,  o);
    }
    __shared__ float s1[8], s2[8];
    const int lane = t & 31, w = t >> 5;
    if (!lane) { s1[w] = sum; s2[w] = sq; }
    __syncthreads();
    if (w == 0) {
        sum = (lane < 8) ? s1[lane] : 0.f;
        sq  = (lane < 8) ? s2[lane] : 0.f;
        for (int o = 4; o; o >>= 1) {
            sum += __shfl_down_sync(0xffffffffu, sum, o);
            sq  += __shfl_down_sync(0xffffffffu, sq,  o);
        }
        if (!lane) { s1[0] = sum; s2[0] = sq; }
    }
    __syncthreads();
    const float mean = s1[0] * (1.f / HH);
    const float var  = s2[0] * (1.f / HH) - mean * mean;
    const float inv  = rsqrtf(var + 1e-5f);
    const float4 sc0 = ((const float4*)s)[t * 2],   sc1 = ((const float4*)s)[t * 2 + 1];
    const float4 bb0 = ((const float4*)bvec)[t * 2], bb1 = ((const float4*)bvec)[t * 2 + 1];
    const __half2 h0 = __floats2half2_rn((v0.x - mean) * inv * sc0.x + bb0.x,
                                         (v0.y - mean) * inv * sc0.y + bb0.y);
    const __half2 h1 = __floats2half2_rn((v0.z - mean) * inv * sc0.z + bb0.z,
                                         (v0.w - mean) * inv * sc0.w + bb0.w);
    const __half2 h2 = __floats2half2_rn((v1.x - mean) * inv * sc1.x + bb1.x,
                                         (v1.y - mean) * inv * sc1.y + bb1.y);
    const __half2 h3 = __floats2half2_rn((v1.z - mean) * inv * sc1.z + bb1.z,
                                         (v1.w - mean) * inv * sc1.w + bb1.w);
    uint4 o;
    o.x = *(const uint32_t*)&h0; o.y = *(const uint32_t*)&h1;
    o.z = *(const uint32_t*)&h2; o.w = *(const uint32_t*)&h3;
    ((uint4*)(out + (size_t)row * HH))[t] = o;
}

// ---------------------------------------------------------------------------
// Level projection + softmax over D=4 (h fp16): one block per row
// ---------------------------------------------------------------------------
__global__ __launch_bounds__(256) void lvl_kernel(
    const __half* __restrict__ h, const float* __restrict__ W,
    const float* __restrict__ bias, float* __restrict__ lw)
{
    const int row = blockIdx.x;
    const __half* hr = h + (size_t)row * HH;
    float a0 = 0.f, a1 = 0.f, a2 = 0.f, a3 = 0.f;
    for (int i = threadIdx.x; i < HH; i += 256) {
        const float hv = __half2float(hr[i]);
        const float4 w = *(const float4*)(W + (size_t)i * 4);
        a0 = fmaf(hv, w.x, a0); a1 = fmaf(hv, w.y, a1);
        a2 = fmaf(hv, w.z, a2); a3 = fmaf(hv, w.w, a3);
    }
    for (int o = 16; o; o >>= 1) {
        a0 += __shfl_down_sync(0xffffffffu, a0, o);
        a1 += __shfl_down_sync(0xffffffffu, a1, o);
        a2 += __shfl_down_sync(0xffffffffu, a2, o);
        a3 += __shfl_down_sync(0xffffffffu, a3, o);
    }
    __shared__ float red[8][4];
    const int lane = threadIdx.x & 31, w = threadIdx.x >> 5;
    if (!lane) { red[w][0] = a0; red[w][1] = a1; red[w][2] = a2; red[w][3] = a3; }
    __syncthreads();
    if (threadIdx.x == 0) {
        float s[4];
        for (int d = 0; d < 4; d++) {
            s[d] = bias[d];
            for (int ww = 0; ww < 8; ww++) s[d] += red[ww][d];
        }
        float mx = fmaxf(fmaxf(s[0], s[1]), fmaxf(s[2], s[3]));
        float e[4], tot = 0.f;
        for (int d = 0; d < 4; d++) { e[d] = expf(s[d] - mx); tot += e[d]; }
        const float rinv = 1.f / tot;
        for (int d = 0; d < 4; d++) lw[(size_t)row * 4 + d] = e[d] * rinv;
    }
}

__global__ void decay_kernel(const float* __restrict__ td, float* __restrict__ dec)
{
    const int i = blockIdx.x * blockDim.x + threadIdx.x;
    if (i < DD * HH) dec[i] = expf(-expf(td[i]));
}

// attin(half) = sigmoid(r) * sum_d lw_d * (state*decay + k*v); qkv strided v|k|r
__global__ __launch_bounds__(256) void attn_elem_kernel(
    const __half* __restrict__ qkv, const float* __restrict__ lw,
    const float* __restrict__ state, const float* __restrict__ dec,
    __half* __restrict__ attin)
{
    const size_t idx = (size_t)blockIdx.x * 256 + threadIdx.x;
    const int col = (int)(idx & (HH - 1));
    const int row = (int)(idx >> 11);
    const int b   = row >> 11;
    const size_t base = (size_t)row * (3 * HH) + col;
    const float v  = __half2float(qkv[base]);
    const float k  = __half2float(qkv[base + HH]);
    const float rr = __half2float(qkv[base + 2 * HH]);
    const float kv = k * v;
    const float r  = 1.f / (1.f + __expf(-rr));
    const float* lwr = lw + (size_t)row * 4;
    float w = 0.f;
#pragma unroll
    for (int d = 0; d < DD; d++)
        w += lwr[d] * (state[((size_t)b * DD + d) * HH + col] * dec[d * HH + col] + kv);
    attin[idx] = __float2half(r * w);
}

// km(half) = h2*tmk + shift(h2)*(1-tmk)
__global__ __launch_bounds__(256) void km_kernel(
    const __half* __restrict__ h2, const float* __restrict__ cm,
    const float* __restrict__ tmk, __half* __restrict__ km)
{
    const size_t idx = (size_t)blockIdx.x * 256 + threadIdx.x;
    const int col = (int)(idx & (HH - 1));
    const int row = (int)(idx >> 11);
    const int t = row & (TT - 1);
    const int b = row >> 11;
    const float prev = (t == 0) ? cm[(size_t)b * HH + col] : __half2float(h2[idx - HH]);
    const float tk = tmk[col];
    km[idx] = __float2half(__half2float(h2[idx]) * tk + prev * (1.f - tk));
}

// out = x1 + val * sigmoid(gate); vg strided val|gate
__global__ __launch_bounds__(256) void final_kernel(
    const float* __restrict__ x1, const float* __restrict__ vg,
    float* __restrict__ out)
{
    const size_t idx = (size_t)blockIdx.x * 256 + threadIdx.x;
    const int col = (int)(idx & (HH - 1));
    const int row = (int)(idx >> 11);
    const size_t base = (size_t)row * (2 * HH) + col;
    const float g = 1.f / (1.f + __expf(-vg[base + HH]));
    out[idx] = x1[idx] + vg[base] * g;
}

// ---------------------------------------------------------------------------
extern "C" void kernel_launch(void* const* d_in, const int* in_sizes, int n_in,
                              void* d_out, int out_size)
{
    const float* x       = (const float*)d_in[0];
    const float* att_st  = (const float*)d_in[1];
    const float* cm_st   = (const float*)d_in[2];
    const float* ln1_s   = (const float*)d_in[3];
    const float* ln1_b   = (const float*)d_in[4];
    const float* ln2_s   = (const float*)d_in[5];
    const float* ln2_b   = (const float*)d_in[6];
    const float* td      = (const float*)d_in[7];
    const float* lvl_w   = (const float*)d_in[8];
    const float* lvl_b   = (const float*)d_in[9];
    const float* Wv      = (const float*)d_in[10];
    const float* Wk      = (const float*)d_in[11];
    const float* Wr      = (const float*)d_in[12];
    const float* Wo      = (const float*)d_in[13];
    const float* tmk     = (const float*)d_in[14];
    const float* Wkey    = (const float*)d_in[15];
    const float* Wval    = (const float*)d_in[16];
    const float* Wgate   = (const float*)d_in[17];
    float* out = (float*)d_out;

    __half *hh, *att, *kkh, *qkv;
    float *vg, *x1, *lw, *dec;
    __half *WqkvT, *WoT, *WkeyT, *WvgT;
    cudaGetSymbolAddress((void**)&hh,   g_hh);
    cudaGetSymbolAddress((void**)&att,  g_att);
    cudaGetSymbolAddress((void**)&kkh,  g_kkh);
    cudaGetSymbolAddress((void**)&qkv,  g_qkv);
    cudaGetSymbolAddress((void**)&vg,   g_vg);
    cudaGetSymbolAddress((void**)&x1,   g_x1);
    cudaGetSymbolAddress((void**)&lw,   g_lw);
    cudaGetSymbolAddress((void**)&dec,  g_dec);
    cudaGetSymbolAddress((void**)&WqkvT, g_WqkvT);
    cudaGetSymbolAddress((void**)&WoT,   g_WoT);
    cudaGetSymbolAddress((void**)&WkeyT, g_WkeyT);
    cudaGetSymbolAddress((void**)&WvgT,  g_WvgT);

    // opt-in dynamic smem for all GEMM instantiations
    cudaFuncSetAttribute(mma_gemm_kernel<0, __half>, cudaFuncAttributeMaxDynamicSharedMemorySize, GEMM_SMEM);
    cudaFuncSetAttribute(mma_gemm_kernel<0, float>,  cudaFuncAttributeMaxDynamicSharedMemorySize, GEMM_SMEM);
    cudaFuncSetAttribute(mma_gemm_kernel<1, float>,  cudaFuncAttributeMaxDynamicSharedMemorySize, GEMM_SMEM);
    cudaFuncSetAttribute(mma_gemm_kernel<2, __half>, cudaFuncAttributeMaxDynamicSharedMemorySize, GEMM_SMEM);

    const dim3 tb(32, 8);
    // Batched weight transposes (fp32 -> fp16), out[N,K] = in[K,N]^T
    transpose_h4_kernel<<<dim3(HH/32, HH/32, 4), tb>>>(
        Wv, Wk, Wr, Wo,
        WqkvT, WqkvT + (size_t)HH * HH, WqkvT + (size_t)2 * HH * HH, WoT,
        HH, HH);
    transpose_h4_kernel<<<dim3(HH/32, FFN/32, 2), tb>>>(
        Wval, Wgate, Wval, Wgate,
        WvgT, WvgT + (size_t)HH * FFN, WvgT, WvgT + (size_t)HH * FFN,
        FFN, HH);
    transpose_h4_kernel<<<dim3(FFN/32, HH/32, 1), tb>>>(
        Wkey, Wkey, Wkey, Wkey, WkeyT, WkeyT, WkeyT, WkeyT, HH, FFN);

    const dim3 gQKV(3 * HH / 128, MM / 128);   // (48, 64)
    const dim3 gHHd(HH / 128, MM / 128);       // (16, 64)
    const dim3 gFF (FFN / 128, MM / 128);      // (64, 64)
    const dim3 gVG (2 * HH / 128, MM / 128);   // (32, 64)
    const int ELEM_BLKS = (MM * HH) / 256;

    // --- attention half ---
    ln_kernel<<<MM, 256>>>(x, ln1_s, ln1_b, hh);
    mma_gemm_kernel<0, __half><<<gQKV, 128, GEMM_SMEM>>>(hh, WqkvT, nullptr, qkv, MM, 3 * HH, HH);
    lvl_kernel<<<MM, 256>>>(hh, lvl_w, lvl_b, lw);
    decay_kernel<<<(DD * HH + 255) / 256, 256>>>(td, dec);
    attn_elem_kernel<<<ELEM_BLKS, 256>>>(qkv, lw, att_st, dec, att);
    mma_gemm_kernel<1, float><<<gHHd, 128, GEMM_SMEM>>>(att, WoT, x, x1, MM, HH, HH);

    // --- channel-mix half ---
    ln_kernel<<<MM, 256>>>(x1, ln2_s, ln2_b, hh);                          // h2 -> hh
    km_kernel<<<ELEM_BLKS, 256>>>(hh, cm_st, tmk, att);                    // km -> att
    mma_gemm_kernel<2, __half><<<gFF, 128, GEMM_SMEM>>>(att, WkeyT, nullptr, kkh, MM, FFN, HH);
    mma_gemm_kernel<0, float><<<gVG, 128, GEMM_SMEM>>>(kkh, WvgT, nullptr, vg, MM, 2 * HH, FFN);
    final_kernel<<<ELEM_BLKS, 256>>>(x1, vg, out);
}

// round 16
// speedup vs baseline: 1.0314x; 1.0314x over previous
#include <cuda_runtime.h>
#include <cuda_fp16.h>
#include <cstdint>

// Problem constants
#define BB 4
#define TT 2048
#define HH 2048
#define DD 4
#define FFN 8192
#define MM (BB * TT)          // 8192 tokens

// Scratch (device globals: allocation-free per harness rules)
__device__ __half g_hh  [MM * HH];        // h (LN1) -> later h2 (LN2)
__device__ __half g_att [MM * HH];        // attin -> later km
__device__ __half g_kkh [MM * FFN];       // kk (half)
__device__ __half g_qkv [MM * 3 * HH];    // fused v|k|r outputs
__device__ float  g_vg  [MM * 2 * HH];    // fused val|gate outputs
__device__ float  g_x1  [MM * HH];        // x1
__device__ float  g_lw  [MM * DD];        // level softmax weights
__device__ float  g_dec [DD * HH];        // decay
// Transposed fp16 weights ([N,K] row-major for mma.sync row.col B operand)
__device__ __half g_WqkvT[3 * HH * HH];   // WvT | WkT | WrT (row blocks)
__device__ __half g_WoT  [HH * HH];
__device__ __half g_WkeyT[FFN * HH];
__device__ __half g_WvgT [2 * HH * FFN];  // WvalT | WgateT (row blocks)

// ---------------------------------------------------------------------------
__device__ __forceinline__ void mma_f16(float c[4], const uint32_t a[4], const uint32_t b[2]) {
    asm volatile(
        "mma.sync.aligned.m16n8k16.row.col.f32.f16.f16.f32 "
        "{%0,%1,%2,%3}, {%4,%5,%6,%7}, {%8,%9}, {%0,%1,%2,%3};"
        : "+f"(c[0]), "+f"(c[1]), "+f"(c[2]), "+f"(c[3])
        : "r"(a[0]), "r"(a[1]), "r"(a[2]), "r"(a[3]), "r"(b[0]), "r"(b[1]));
}

__device__ __forceinline__ void ldsm_x4(uint32_t& r0, uint32_t& r1, uint32_t& r2, uint32_t& r3,
                                        uint32_t addr) {
    asm volatile("ldmatrix.sync.aligned.m8n8.x4.shared.b16 {%0,%1,%2,%3}, [%4];"
                 : "=r"(r0), "=r"(r1), "=r"(r2), "=r"(r3) : "r"(addr));
}

__device__ __forceinline__ void cp_async16(uint32_t smem_addr, const void* gptr) {
    asm volatile("cp.async.ca.shared.global [%0], [%1], 16;" :: "r"(smem_addr), "l"(gptr));
}
__device__ __forceinline__ void cp_commit() {
    asm volatile("cp.async.commit_group;" ::: "memory");
}
__device__ __forceinline__ void cp_wait1() {
    asm volatile("cp.async.wait_group 1;" ::: "memory");
}

// ===========================================================================
// Tensor-core fp16 GEMM (fp32 accum): C[M,N] = A[M,K] @ Bt[N,K]^T
// Block tile 128x128, BK=32, 128 threads (4 warps = 2x2), warp tile 64x64.
// 3-stage cp.async pipeline (wait_group 1) + double-buffered ldmatrix frags.
// EPI: 0 plain, 1 +Res(float), 2 relu(.)^2.  OutT: float or __half.
// ===========================================================================
#define STAGE_BYTES 20480
#define GEMM_SMEM (3 * STAGE_BYTES)

template <int EPI, typename OutT>
__global__ __launch_bounds__(128, 2) void mma_gemm_kernel(
    const __half* __restrict__ A, const __half* __restrict__ Bt,
    const float* __restrict__ Res, OutT* __restrict__ C,
    int M, int N, int K)
{
    extern __shared__ uint32_t smem[];   // [3][256][20]; rows 0-127 A, 128-255 B
    const uint32_t smem_base = (uint32_t)__cvta_generic_to_shared(smem);

    const int tid = threadIdx.x;
    const int wid = tid >> 5, lane = tid & 31;
    const int wm = wid & 1, wn = wid >> 1;        // 2(m) x 2(n) warp grid
    const int group = lane >> 2, tg = lane & 3;   // mma fragment coords
    const int bm = blockIdx.y * 128, bn = blockIdx.x * 128;

    const __half* Arow = A  + (size_t)(bm + tid) * K;
    const __half* Brow = Bt + (size_t)(bn + tid) * K;
    const uint32_t sA = smem_base + tid * 80;
    const uint32_t sB = smem_base + (128 + tid) * 80;

    const int arow_l = wm * 64 + (lane & 7) + ((lane >> 3) & 1) * 8;
    const int acol_l = (lane >> 4) << 2;
    const int brow_l = wn * 64 + ((lane >> 4) << 3) + (lane & 7);
    const int bcol_l = ((lane >> 3) & 1) << 2;
    const uint32_t aoff = (uint32_t)(arow_l * 80 + acol_l * 4);
    const uint32_t boff = (uint32_t)((128 + brow_l) * 80 + bcol_l * 4);

    auto load_async = [&](int k0, int st) {
        const uint32_t off = (uint32_t)st * STAGE_BYTES;
#pragma unroll
        for (int cg = 0; cg < 4; cg++) {
            cp_async16(sA + off + cg * 16, Arow + k0 + cg * 8);
            cp_async16(sB + off + cg * 16, Brow + k0 + cg * 8);
        }
        cp_commit();
    };

    auto ldfrag = [&](int st, int kb, uint32_t af[4][4], uint32_t bf[8][2]) {
        const uint32_t sb = smem_base + (uint32_t)st * STAGE_BYTES + (uint32_t)kb;
#pragma unroll
        for (int mi = 0; mi < 4; mi++)
            ldsm_x4(af[mi][0], af[mi][1], af[mi][2], af[mi][3], sb + aoff + mi * 1280);
#pragma unroll
        for (int p = 0; p < 4; p++)
            ldsm_x4(bf[2 * p][0], bf[2 * p][1], bf[2 * p + 1][0], bf[2 * p + 1][1],
                    sb + boff + p * 1280);
    };

    float c[4][8][4];
#pragma unroll
    for (int mi = 0; mi < 4; mi++)
#pragma unroll
        for (int ni = 0; ni < 8; ni++)
#pragma unroll
            for (int j = 0; j < 4; j++) c[mi][ni][j] = 0.f;

    auto compute = [&](uint32_t af[4][4], uint32_t bf[8][2]) {
#pragma unroll
        for (int mi = 0; mi < 4; mi++)
#pragma unroll
            for (int ni = 0; ni < 8; ni++)
                mma_f16(c[mi][ni], af[mi], bf[ni]);
    };

    const int nt = K >> 5;
    load_async(0, 0);
    load_async(32, 1);
    cp_wait1();
    __syncthreads();

    uint32_t af0[4][4], bf0[8][2], af1[4][4], bf1[8][2];
    ldfrag(0, 0, af0, bf0);

    for (int t = 0; t < nt; ++t) {
        const int buf = t % 3;
        if (t + 2 < nt) load_async((t + 2) << 5, (t + 2) % 3);
        else cp_commit();
        ldfrag(buf, 32, af1, bf1);
        compute(af0, bf0);
        compute(af1, bf1);
        cp_wait1();
        __syncthreads();
        if (t + 1 < nt) ldfrag((t + 1) % 3, 0, af0, bf0);
    }

    // epilogue
#pragma unroll
    for (int mi = 0; mi < 4; mi++) {
        const int m0 = bm + wm * 64 + mi * 16 + group;
#pragma unroll
        for (int ni = 0; ni < 8; ni++) {
            const int n0 = bn + wn * 64 + ni * 8 + tg * 2;
            float2 lo = make_float2(c[mi][ni][0], c[mi][ni][1]);
            float2 hi = make_float2(c[mi][ni][2], c[mi][ni][3]);
            if (EPI == 1) {
                const float2 r0 = *(const float2*)(Res + (size_t)m0 * N + n0);
                const float2 r1 = *(const float2*)(Res + (size_t)(m0 + 8) * N + n0);
                lo.x += r0.x; lo.y += r0.y; hi.x += r1.x; hi.y += r1.y;
            }
            if (EPI == 2) {
                lo.x = fmaxf(lo.x, 0.f); lo.x *= lo.x;
                lo.y = fmaxf(lo.y, 0.f); lo.y *= lo.y;
                hi.x = fmaxf(hi.x, 0.f); hi.x *= hi.x;
                hi.y = fmaxf(hi.y, 0.f); hi.y *= hi.y;
            }
            if (sizeof(OutT) == 2) {
                *(__half2*)((__half*)C + (size_t)m0 * N + n0)       = __floats2half2_rn(lo.x, lo.y);
                *(__half2*)((__half*)C + (size_t)(m0 + 8) * N + n0) = __floats2half2_rn(hi.x, hi.y);
            } else {
                *(float2*)((float*)C + (size_t)m0 * N + n0)       = lo;
                *(float2*)((float*)C + (size_t)(m0 + 8) * N + n0) = hi;
            }
        }
    }
}

// ---------------------------------------------------------------------------
// Batched transpose + fp16 convert: in[z][R,C] fp32 -> out[z][C,R] fp16
// ---------------------------------------------------------------------------
__global__ __launch_bounds__(256) void transpose_h4_kernel(
    const float* i0, const float* i1, const float* i2, const float* i3,
    __half* o0, __half* o1, __half* o2, __half* o3, int R, int C)
{
    const int z = blockIdx.z;
    const float* in = (z == 0) ? i0 : (z == 1) ? i1 : (z == 2) ? i2 : i3;
    __half* out     = (z == 0) ? o0 : (z == 1) ? o1 : (z == 2) ? o2 : o3;
    __shared__ float tile[32][33];
    const int c0 = blockIdx.x * 32, r0 = blockIdx.y * 32;
    for (int i = threadIdx.y; i < 32; i += 8)
        tile[i][threadIdx.x] = in[(size_t)(r0 + i) * C + c0 + threadIdx.x];
    __syncthreads();
    for (int i = threadIdx.y; i < 32; i += 8)
        out[(size_t)(c0 + i) * R + r0 + threadIdx.x] = __float2half(tile[threadIdx.x][i]);
}

// ---------------------------------------------------------------------------
// Single-pass LayerNorm -> fp16: row cached in registers (8 floats/thread)
// ---------------------------------------------------------------------------
__global__ __launch_bounds__(256) void ln_kernel(
    const float* __restrict__ x, const float* __restrict__ s,
    const float* __restrict__ bvec, __half* __restrict__ out)
{
    const int row = blockIdx.x;
    const int t = threadIdx.x;
    const float4* xr = (const float4*)(x + (size_t)row * HH);
    const float4 v0 = xr[t * 2], v1 = xr[t * 2 + 1];
    float sum = v0.x + v0.y + v0.z + v0.w + v1.x + v1.y + v1.z + v1.w;
    float sq  = v0.x * v0.x + v0.y * v0.y + v0.z * v0.z + v0.w * v0.w
              + v1.x * v1.x + v1.y * v1.y + v1.z * v1.z + v1.w * v1.w;
    for (int o = 16; o; o >>= 1) {
        sum += __shfl_down_sync(0xffffffffu, sum, o);
        sq  += __shfl_down_sync(0xffffffffu, sq,  o);
    }
    __shared__ float s1[8], s2[8];
    const int lane = t & 31, w = t >> 5;
    if (!lane) { s1[w] = sum; s2[w] = sq; }
    __syncthreads();
    if (w == 0) {
        sum = (lane < 8) ? s1[lane] : 0.f;
        sq  = (lane < 8) ? s2[lane] : 0.f;
        for (int o = 4; o; o >>= 1) {
            sum += __shfl_down_sync(0xffffffffu, sum, o);
            sq  += __shfl_down_sync(0xffffffffu, sq,  o);
        }
        if (!lane) { s1[0] = sum; s2[0] = sq; }
    }
    __syncthreads();
    const float mean = s1[0] * (1.f / HH);
    const float var  = s2[0] * (1.f / HH) - mean * mean;
    const float inv  = rsqrtf(var + 1e-5f);
    const float4 sc0 = ((const float4*)s)[t * 2],   sc1 = ((const float4*)s)[t * 2 + 1];
    const float4 bb0 = ((const float4*)bvec)[t * 2], bb1 = ((const float4*)bvec)[t * 2 + 1];
    const __half2 h0 = __floats2half2_rn((v0.x - mean) * inv * sc0.x + bb0.x,
                                         (v0.y - mean) * inv * sc0.y + bb0.y);
    const __half2 h1 = __floats2half2_rn((v0.z - mean) * inv * sc0.z + bb0.z,
                                         (v0.w - mean) * inv * sc0.w + bb0.w);
    const __half2 h2 = __floats2half2_rn((v1.x - mean) * inv * sc1.x + bb1.x,
                                         (v1.y - mean) * inv * sc1.y + bb1.y);
    const __half2 h3 = __floats2half2_rn((v1.z - mean) * inv * sc1.z + bb1.z,
                                         (v1.w - mean) * inv * sc1.w + bb1.w);
    uint4 o;
    o.x = *(const uint32_t*)&h0; o.y = *(const uint32_t*)&h1;
    o.z = *(const uint32_t*)&h2; o.w = *(const uint32_t*)&h3;
    ((uint4*)(out + (size_t)row * HH))[t] = o;
}

// ---------------------------------------------------------------------------
// Level projection + softmax over D=4 (h fp16): one block per row
// ---------------------------------------------------------------------------
__global__ __launch_bounds__(256) void lvl_kernel(
    const __half* __restrict__ h, const float* __restrict__ W,
    const float* __restrict__ bias, float* __restrict__ lw)
{
    const int row = blockIdx.x;
    const __half* hr = h + (size_t)row * HH;
    float a0 = 0.f, a1 = 0.f, a2 = 0.f, a3 = 0.f;
    for (int i = threadIdx.x; i < HH; i += 256) {
        const float hv = __half2float(hr[i]);
        const float4 w = *(const float4*)(W + (size_t)i * 4);
        a0 = fmaf(hv, w.x, a0); a1 = fmaf(hv, w.y, a1);
        a2 = fmaf(hv, w.z, a2); a3 = fmaf(hv, w.w, a3);
    }
    for (int o = 16; o; o >>= 1) {
        a0 += __shfl_down_sync(0xffffffffu, a0, o);
        a1 += __shfl_down_sync(0xffffffffu, a1, o);
        a2 += __shfl_down_sync(0xffffffffu, a2, o);
        a3 += __shfl_down_sync(0xffffffffu, a3, o);
    }
    __shared__ float red[8][4];
    const int lane = threadIdx.x & 31, w = threadIdx.x >> 5;
    if (!lane) { red[w][0] = a0; red[w][1] = a1; red[w][2] = a2; red[w][3] = a3; }
    __syncthreads();
    if (threadIdx.x == 0) {
        float s[4];
        for (int d = 0; d < 4; d++) {
            s[d] = bias[d];
            for (int ww = 0; ww < 8; ww++) s[d] += red[ww][d];
        }
        float mx = fmaxf(fmaxf(s[0], s[1]), fmaxf(s[2], s[3]));
        float e[4], tot = 0.f;
        for (int d = 0; d < 4; d++) { e[d] = expf(s[d] - mx); tot += e[d]; }
        const float rinv = 1.f / tot;
        for (int d = 0; d < 4; d++) lw[(size_t)row * 4 + d] = e[d] * rinv;
    }
}

__global__ void decay_kernel(const float* __restrict__ td, float* __restrict__ dec)
{
    const int i = blockIdx.x * blockDim.x + threadIdx.x;
    if (i < DD * HH) dec[i] = expf(-expf(td[i]));
}

// attin(half) = sigmoid(r) * sum_d lw_d * (state*decay + k*v); qkv strided v|k|r
__global__ __launch_bounds__(256) void attn_elem_kernel(
    const __half* __restrict__ qkv, const float* __restrict__ lw,
    const float* __restrict__ state, const float* __restrict__ dec,
    __half* __restrict__ attin)
{
    const size_t idx = (size_t)blockIdx.x * 256 + threadIdx.x;
    const int col = (int)(idx & (HH - 1));
    const int row = (int)(idx >> 11);
    const int b   = row >> 11;
    const size_t base = (size_t)row * (3 * HH) + col;
    const float v  = __half2float(qkv[base]);
    const float k  = __half2float(qkv[base + HH]);
    const float rr = __half2float(qkv[base + 2 * HH]);
    const float kv = k * v;
    const float r  = 1.f / (1.f + __expf(-rr));
    const float* lwr = lw + (size_t)row * 4;
    float w = 0.f;
#pragma unroll
    for (int d = 0; d < DD; d++)
        w += lwr[d] * (state[((size_t)b * DD + d) * HH + col] * dec[d * HH + col] + kv);
    attin[idx] = __float2half(r * w);
}

// km(half) = h2*tmk + shift(h2)*(1-tmk)
__global__ __launch_bounds__(256) void km_kernel(
    const __half* __restrict__ h2, const float* __restrict__ cm,
    const float* __restrict__ tmk, __half* __restrict__ km)
{
    const size_t idx = (size_t)blockIdx.x * 256 + threadIdx.x;
    const int col = (int)(idx & (HH - 1));
    const int row = (int)(idx >> 11);
    const int t = row & (TT - 1);
    const int b = row >> 11;
    const float prev = (t == 0) ? cm[(size_t)b * HH + col] : __half2float(h2[idx - HH]);
    const float tk = tmk[col];
    km[idx] = __float2half(__half2float(h2[idx]) * tk + prev * (1.f - tk));
}

// out = x1 + val * sigmoid(gate); vg strided val|gate
__global__ __launch_bounds__(256) void final_kernel(
    const float* __restrict__ x1, const float* __restrict__ vg,
    float* __restrict__ out)
{
    const size_t idx = (size_t)blockIdx.x * 256 + threadIdx.x;
    const int col = (int)(idx & (HH - 1));
    const int row = (int)(idx >> 11);
    const size_t base = (size_t)row * (2 * HH) + col;
    const float g = 1.f / (1.f + __expf(-vg[base + HH]));
    out[idx] = x1[idx] + vg[base] * g;
}

// ---------------------------------------------------------------------------
extern "C" void kernel_launch(void* const* d_in, const int* in_sizes, int n_in,
                              void* d_out, int out_size)
{
    const float* x       = (const float*)d_in[0];
    const float* att_st  = (const float*)d_in[1];
    const float* cm_st   = (const float*)d_in[2];
    const float* ln1_s   = (const float*)d_in[3];
    const float* ln1_b   = (const float*)d_in[4];
    const float* ln2_s   = (const float*)d_in[5];
    const float* ln2_b   = (const float*)d_in[6];
    const float* td      = (const float*)d_in[7];
    const float* lvl_w   = (const float*)d_in[8];
    const float* lvl_b   = (const float*)d_in[9];
    const float* Wv      = (const float*)d_in[10];
    const float* Wk      = (const float*)d_in[11];
    const float* Wr      = (const float*)d_in[12];
    const float* Wo      = (const float*)d_in[13];
    const float* tmk     = (const float*)d_in[14];
    const float* Wkey    = (const float*)d_in[15];
    const float* Wval    = (const float*)d_in[16];
    const float* Wgate   = (const float*)d_in[17];
    float* out = (float*)d_out;

    __half *hh, *att, *kkh, *qkv;
    float *vg, *x1, *lw, *dec;
    __half *WqkvT, *WoT, *WkeyT, *WvgT;
    cudaGetSymbolAddress((void**)&hh,   g_hh);
    cudaGetSymbolAddress((void**)&att,  g_att);
    cudaGetSymbolAddress((void**)&kkh,  g_kkh);
    cudaGetSymbolAddress((void**)&qkv,  g_qkv);
    cudaGetSymbolAddress((void**)&vg,   g_vg);
    cudaGetSymbolAddress((void**)&x1,   g_x1);
    cudaGetSymbolAddress((void**)&lw,   g_lw);
    cudaGetSymbolAddress((void**)&dec,  g_dec);
    cudaGetSymbolAddress((void**)&WqkvT, g_WqkvT);
    cudaGetSymbolAddress((void**)&WoT,   g_WoT);
    cudaGetSymbolAddress((void**)&WkeyT, g_WkeyT);
    cudaGetSymbolAddress((void**)&WvgT,  g_WvgT);

    // opt-in dynamic smem for all GEMM instantiations
    cudaFuncSetAttribute(mma_gemm_kernel<0, __half>, cudaFuncAttributeMaxDynamicSharedMemorySize, GEMM_SMEM);
    cudaFuncSetAttribute(mma_gemm_kernel<0, float>,  cudaFuncAttributeMaxDynamicSharedMemorySize, GEMM_SMEM);
    cudaFuncSetAttribute(mma_gemm_kernel<1, float>,  cudaFuncAttributeMaxDynamicSharedMemorySize, GEMM_SMEM);
    cudaFuncSetAttribute(mma_gemm_kernel<2, __half>, cudaFuncAttributeMaxDynamicSharedMemorySize, GEMM_SMEM);

    const dim3 tb(32, 8);
    // Batched weight transposes (fp32 -> fp16), out[N,K] = in[K,N]^T
    transpose_h4_kernel<<<dim3(HH/32, HH/32, 4), tb>>>(
        Wv, Wk, Wr, Wo,
        WqkvT, WqkvT + (size_t)HH * HH, WqkvT + (size_t)2 * HH * HH, WoT,
        HH, HH);
    transpose_h4_kernel<<<dim3(HH/32, FFN/32, 2), tb>>>(
        Wval, Wgate, Wval, Wgate,
        WvgT, WvgT + (size_t)HH * FFN, WvgT, WvgT + (size_t)HH * FFN,
        FFN, HH);
    transpose_h4_kernel<<<dim3(FFN/32, HH/32, 1), tb>>>(
        Wkey, Wkey, Wkey, Wkey, WkeyT, WkeyT, WkeyT, WkeyT, HH, FFN);

    const dim3 gQKV(3 * HH / 128, MM / 128);   // (48, 64)
    const dim3 gHHd(HH / 128, MM / 128);       // (16, 64)
    const dim3 gFF (FFN / 128, MM / 128);      // (64, 64)
    const dim3 gVG (2 * HH / 128, MM / 128);   // (32, 64)
    const int ELEM_BLKS = (MM * HH) / 256;

    // --- attention half ---
    ln_kernel<<<MM, 256>>>(x, ln1_s, ln1_b, hh);
    mma_gemm_kernel<0, __half><<<gQKV, 128, GEMM_SMEM>>>(hh, WqkvT, nullptr, qkv, MM, 3 * HH, HH);
    lvl_kernel<<<MM, 256>>>(hh, lvl_w, lvl_b, lw);
    decay_kernel<<<(DD * HH + 255) / 256, 256>>>(td, dec);
    attn_elem_kernel<<<ELEM_BLKS, 256>>>(qkv, lw, att_st, dec, att);
    mma_gemm_kernel<1, float><<<gHHd, 128, GEMM_SMEM>>>(att, WoT, x, x1, MM, HH, HH);

    // --- channel-mix half ---
    ln_kernel<<<MM, 256>>>(x1, ln2_s, ln2_b, hh);                          // h2 -> hh
    km_kernel<<<ELEM_BLKS, 256>>>(hh, cm_st, tmk, att);                    // km -> att
    mma_gemm_kernel<2, __half><<<gFF, 128, GEMM_SMEM>>>(att, WkeyT, nullptr, kkh, MM, FFN, HH);
    mma_gemm_kernel<0, float><<<gVG, 128, GEMM_SMEM>>>(kkh, WvgT, nullptr, vg, MM, 2 * HH, FFN);
    final_kernel<<<ELEM_BLKS, 256>>>(x1, vg, out);
}